// round 15
// baseline (speedup 1.0000x reference)
#include <cuda_runtime.h>
#include <cuda_bf16.h>
#include <cstdint>
#include <math.h>

#define BSZ   4096
#define FD    768
#define PD    500
#define ZD    300
#define RNUM  10
#define UNUM  10

// A segment row offsets (order: t, v, u, rt, rv, ru)
#define T_OFF   0
#define V_OFF   4096
#define U_OFF   8192
#define RT_OFF  12288
#define RV_OFF  53248
#define RU_OFF  94208
#define XP_ROWS 135168
#define M_BASE  24576          // 4096*6 compact rows
#define M_ROWS  24596          // + 20 sample-0 pair rows
#define M_PAD_HG 24704         // 193*128

#define P1K 2176               // 17*128 (>=2100)
#define P2K 896                // 7*128  (>=800)

// -------------------- static scratch (no allocations allowed) -------------------
__device__ uint8_t g_Abf[(size_t)XP_ROWS * FD];      // proj inputs e4m3
__device__ uint8_t g_Bbf[6 * 512 * FD];              // proj weights e4m3
__device__ float   g_M  [(size_t)M_ROWS * PD];       // group-summed tanh outputs (fp32)
__device__ uint8_t g_hgA[(size_t)M_PAD_HG * 512];    // hg A e4m3 (Kpad 512)
__device__ uint8_t g_hgW[(size_t)384 * 512];
__device__ float   g_Z  [(size_t)M_ROWS * ZD];
__device__ uint8_t g_p1A[(size_t)BSZ * P1K];         // feat e4m3
__device__ uint8_t g_p1W[(size_t)896 * P1K];
__device__ uint8_t g_p2A[(size_t)BSZ * P2K];         // h1 e4m3
__device__ uint8_t g_p2W[(size_t)256 * P2K];
__device__ float   g_H2 [(size_t)BSZ * 200];

__constant__ int c_rowbase[6] = {T_OFF, V_OFF, U_OFF, RT_OFF, RV_OFF, RU_OFF};

// ============================ PTX helpers =======================================
__device__ __forceinline__ uint32_t smem_u32(const void* p) {
    uint32_t a;
    asm("{ .reg .u64 t; cvta.to.shared.u64 t, %1; cvt.u32.u64 %0, t; }" : "=r"(a) : "l"(p));
    return a;
}
__device__ __forceinline__ void cp16(uint32_t dst, const void* src) {
    asm volatile("cp.async.cg.shared.global [%0], [%1], 16;" :: "r"(dst), "l"(src));
}
#define CP_COMMIT() asm volatile("cp.async.commit_group;" ::: "memory")
#define CP_WAIT0()  asm volatile("cp.async.wait_group 0;" ::: "memory")
#define CP_WAIT1()  asm volatile("cp.async.wait_group 1;" ::: "memory")

__device__ __forceinline__ void ldsm_x4(uint32_t& r0, uint32_t& r1, uint32_t& r2, uint32_t& r3,
                                        uint32_t addr) {
    asm volatile("ldmatrix.sync.aligned.m8n8.x4.shared.b16 {%0,%1,%2,%3}, [%4];"
                 : "=r"(r0), "=r"(r1), "=r"(r2), "=r"(r3) : "r"(addr));
}
// fp8 e4m3 MMA: D(16x8,f32) += A(16x32,e4m3) * B(8x32,e4m3)^T
__device__ __forceinline__ void mma16832f8(float* d, const uint32_t* a, const uint32_t* b) {
    asm volatile("mma.sync.aligned.m16n8k32.row.col.f32.e4m3.e4m3.f32 "
                 "{%0,%1,%2,%3}, {%4,%5,%6,%7}, {%8,%9}, {%0,%1,%2,%3};"
                 : "+f"(d[0]), "+f"(d[1]), "+f"(d[2]), "+f"(d[3])
                 : "r"(a[0]), "r"(a[1]), "r"(a[2]), "r"(a[3]), "r"(b[0]), "r"(b[1]));
}
// pack 2 floats -> 2 e4m3 bytes (lo byte = v0)
__device__ __forceinline__ unsigned short f8pack2(float v0, float v1) {
    unsigned short h;
    asm("cvt.rn.satfinite.e4m3x2.f32 %0, %1, %2;" : "=h"(h) : "f"(v1), "f"(v0));
    return h;
}
#define SWZ128(b)  ((b) ^ (((b) >> 3) & 0x70))
#define SM_STAGE 32768   // A(16K) + B(16K), each tile = 128 rows x 128 fp8
#define SMEM_REQ 69632   // 2 stages + room for 128x132 fp32 reduction staging

// chunk load: 128x128 A fp8 tile + 128x128 B fp8 tile (SW128); koff in elements
__device__ __forceinline__ void load_chunk1(
    const uint8_t* __restrict__ A, const uint8_t* __restrict__ B,
    int strideA, int strideB, int koff, int n0, uint32_t sbase, int tid)
{
    const int r = tid >> 3, q = tid & 7;
    const uint32_t sa  = sbase + SWZ128(r * 128 + q * 16);
    const uint32_t sbB = sbase + 16384 + SWZ128(r * 128 + q * 16);
#pragma unroll
    for (int i = 0; i < 4; i++)
        cp16(sa + i * 4096, A + (size_t)(r + i * 32) * strideA + koff + q * 16);
#pragma unroll
    for (int i = 0; i < 4; i++)
        cp16(sbB + i * 4096, B + (size_t)(n0 + r + i * 32) * strideB + koff + q * 16);
}

// compute one 128-K fp8 chunk (4 ks-steps of k=32)
__device__ __forceinline__ void compute_chunk1(uint32_t base, int warp_m, int warp_n,
                                               int lane, float acc[4][4][4])
{
#pragma unroll
    for (int ks = 0; ks < 4; ks++) {
        uint32_t a[4][4], b[2][4];
#pragma unroll
        for (int mt = 0; mt < 4; mt++) {
            int row = warp_m * 64 + mt * 16 + (lane & 15);
            int byo = row * 128 + ks * 32 + ((lane >> 4) & 1) * 16;
            ldsm_x4(a[mt][0], a[mt][1], a[mt][2], a[mt][3], base + SWZ128(byo));
        }
#pragma unroll
        for (int np = 0; np < 2; np++) {
            int nrow = warp_n * 32 + np * 16 + ((lane >> 4) & 1) * 8 + (lane & 7);
            int byo = nrow * 128 + ks * 32 + ((lane >> 3) & 1) * 16;
            ldsm_x4(b[np][0], b[np][1], b[np][2], b[np][3], base + 16384 + SWZ128(byo));
        }
#pragma unroll
        for (int mt = 0; mt < 4; mt++)
#pragma unroll
            for (int nt = 0; nt < 4; nt++)
                mma16832f8(acc[mt][nt], a[mt], &b[nt >> 1][(nt & 1) * 2]);
    }
}

// ======================= conversion kernel ======================================
// float [rows_src x Kreal] -> e4m3 [rows_dst x Kpad], zero padded; Kpad % 4 == 0
__global__ void conv_f8(const float* __restrict__ src, uint8_t* __restrict__ dst,
                        int rows_src, int Kreal, int Kpad, long long total4)
{
    long long i = (long long)blockIdx.x * blockDim.x + threadIdx.x;
    if (i >= total4) return;
    const int K4 = Kpad >> 2;
    int c4 = (int)(i % K4) * 4;
    long long row = i / K4;
    float x[4];
#pragma unroll
    for (int j = 0; j < 4; j++) {
        int col = c4 + j;
        x[j] = (row < rows_src && col < Kreal) ? src[row * Kreal + col] : 0.f;
    }
    unsigned short lo = f8pack2(x[0], x[1]);
    unsigned short hi = f8pack2(x[2], x[3]);
    *reinterpret_cast<uint32_t*>(dst + row * Kpad + c4) =
        ((uint32_t)hi << 16) | (uint32_t)lo;
}

// ================= unified projection GEMM (6 segments, fused epilogue) =========
struct ProjArgs {
    const uint8_t* A;
    const uint8_t* B[6];
    const float* bias[6];
    float* Mo;
};

__global__ __launch_bounds__(256) void proj_gemm(ProjArgs args)
{
    extern __shared__ char smem[];
    const uint32_t sb = smem_u32(smem);
    const int tid = threadIdx.x, lane = tid & 31, wid = tid >> 5;
    const int warp_m = wid >> 2, warp_n = wid & 3;
    const int n0 = blockIdx.x * 128;
    const int ty = blockIdx.y;

    int seg, tstart;
    if (ty < 96)       { seg = ty >> 5; tstart = seg << 5; }
    else if (ty < 416) { seg = 3; tstart = 96; }
    else if (ty < 736) { seg = 4; tstart = 416; }
    else               { seg = 5; tstart = 736; }
    const int tl = ty - tstart;
    const uint8_t* A = args.A + (size_t)(c_rowbase[seg] + tl * 128) * FD;
    const uint8_t* B = args.B[seg];
    const float* bias = args.bias[seg];
    float* Mo = args.Mo;

    float acc[4][4][4];
#pragma unroll
    for (int i = 0; i < 4; i++)
#pragma unroll
        for (int j = 0; j < 4; j++)
#pragma unroll
            for (int k = 0; k < 4; k++) acc[i][j][k] = 0.f;

    const int kc = FD / 128;   // 6
    load_chunk1(A, B, FD, FD, 0, n0, sb, tid);
    CP_COMMIT();
    for (int c = 0; c < kc; c++) {
        if (c + 1 < kc) {
            load_chunk1(A, B, FD, FD, (c + 1) * 128, n0, sb + ((c + 1) & 1) * SM_STAGE, tid);
            CP_COMMIT();
            CP_WAIT1();
        } else CP_WAIT0();
        __syncthreads();
        compute_chunk1(sb + (c & 1) * SM_STAGE, warp_m, warp_n, lane, acc);
        __syncthreads();
    }

    if (seg < 3) {
        // direct: one row per sample -> g_M[(b*6+seg)*500 + n]
#pragma unroll
        for (int mt = 0; mt < 4; mt++) {
            int r0 = warp_m * 64 + mt * 16 + (lane >> 2);
#pragma unroll
            for (int nt = 0; nt < 4; nt++) {
                int c0 = warp_n * 32 + nt * 8 + (lane & 3) * 2;
#pragma unroll
                for (int q = 0; q < 4; q++) {
                    int r = r0 + ((q >> 1) ? 8 : 0);
                    int cc = n0 + c0 + (q & 1);
                    if (cc < PD) {
                        float v = tanhf(acc[mt][nt][q] + bias[cc]);
                        Mo[((size_t)(tl * 128 + r) * 6 + seg) * PD + cc] = v;
                    }
                }
            }
        }
    } else {
        // reduce: stage tanh values in smem, sum per sample, atomicAdd
        float* sred = (float*)smem;
#pragma unroll
        for (int mt = 0; mt < 4; mt++) {
            int r0 = warp_m * 64 + mt * 16 + (lane >> 2);
#pragma unroll
            for (int nt = 0; nt < 4; nt++) {
                int c0 = warp_n * 32 + nt * 8 + (lane & 3) * 2;
#pragma unroll
                for (int q = 0; q < 4; q++) {
                    int r = r0 + ((q >> 1) ? 8 : 0);
                    int cl = c0 + (q & 1);
                    int cc = n0 + cl;
                    float v = tanhf(acc[mt][nt][q] + bias[cc < PD ? cc : PD - 1]);
                    sred[r * 132 + cl] = v;
                }
            }
        }
        __syncthreads();
        const int r0g = tl * 128;
        const int sfirst = r0g / 10, slast = (r0g + 127) / 10;
        const int ns = slast - sfirst + 1;
        for (int idx = tid; idx < ns * 128; idx += 256) {
            int si = idx >> 7, cl = idx & 127;
            int cc = n0 + cl;
            if (cc >= PD) continue;
            int s = sfirst + si;
            int lo = s * 10 - r0g;     if (lo < 0) lo = 0;
            int hi = s * 10 + 9 - r0g; if (hi > 127) hi = 127;
            float sum = 0.f;
            for (int r = lo; r <= hi; r++) sum += sred[r * 132 + cl];
            atomicAdd(&Mo[((size_t)s * 6 + seg) * PD + cc], sum);
        }
        if (tl == 0 && seg != 5) {
            int rb = (seg == 3) ? M_BASE : M_BASE + RNUM;
            for (int idx = tid; idx < 10 * 128; idx += 256) {
                int r = idx >> 7, cl = idx & 127;
                int cc = n0 + cl;
                if (cc < PD) Mo[((size_t)(rb + r)) * PD + cc] = sred[r * 132 + cl];
            }
        }
    }
}

// ===================== generic e4m3 MMA GEMM ====================================
__global__ __launch_bounds__(256) void mma_gemm1(
    const uint8_t* __restrict__ A, const uint8_t* __restrict__ B,
    const float* __restrict__ bias, void* __restrict__ Cout,
    int M, int Nreal, int ostride, int Kpad, int act, int outf8)
{
    extern __shared__ char smem[];
    const uint32_t sb = smem_u32(smem);
    const int tid = threadIdx.x, lane = tid & 31, wid = tid >> 5;
    const int warp_m = wid >> 2, warp_n = wid & 3;
    const int m0 = blockIdx.y * 128, n0 = blockIdx.x * 128;
    const uint8_t* At = A + (size_t)m0 * Kpad;
    const int kc = Kpad >> 7;

    float acc[4][4][4];
#pragma unroll
    for (int i = 0; i < 4; i++)
#pragma unroll
        for (int j = 0; j < 4; j++)
#pragma unroll
            for (int k = 0; k < 4; k++) acc[i][j][k] = 0.f;

    load_chunk1(At, B, Kpad, Kpad, 0, n0, sb, tid);
    CP_COMMIT();
    for (int c = 0; c < kc; c++) {
        if (c + 1 < kc) {
            load_chunk1(At, B, Kpad, Kpad, (c + 1) * 128, n0,
                        sb + ((c + 1) & 1) * SM_STAGE, tid);
            CP_COMMIT();
            CP_WAIT1();
        } else CP_WAIT0();
        __syncthreads();
        compute_chunk1(sb + (c & 1) * SM_STAGE, warp_m, warp_n, lane, acc);
        __syncthreads();
    }

#pragma unroll
    for (int mt = 0; mt < 4; mt++) {
        int r0 = m0 + warp_m * 64 + mt * 16 + (lane >> 2);
#pragma unroll
        for (int nt = 0; nt < 4; nt++) {
            int c0 = n0 + warp_n * 32 + nt * 8 + (lane & 3) * 2;
            if (outf8) {
                if (c0 >= Nreal) continue;   // pair-aligned boundary (Nreal even)
#pragma unroll
                for (int half = 0; half < 2; half++) {
                    int r = r0 + half * 8;
                    if (r >= M) continue;
                    float v0 = acc[mt][nt][half * 2 + 0];
                    float v1 = acc[mt][nt][half * 2 + 1];
                    if (bias) { v0 += bias[c0]; v1 += bias[c0 + 1]; }
                    if (act == 2) { v0 = fmaxf(v0, 0.f); v1 = fmaxf(v1, 0.f); }
                    *reinterpret_cast<unsigned short*>(
                        (uint8_t*)Cout + (size_t)r * ostride + c0) = f8pack2(v0, v1);
                }
            } else {
#pragma unroll
                for (int q = 0; q < 4; q++) {
                    int r = r0 + ((q >> 1) ? 8 : 0);
                    int cc = c0 + (q & 1);
                    if (r < M && cc < Nreal) {
                        float v = acc[mt][nt][q];
                        if (bias) v += bias[cc];
                        if (act == 2) v = fmaxf(v, 0.f);
                        ((float*)Cout)[(size_t)r * ostride + cc] = v;
                    }
                }
            }
        }
    }
}

// ------------ K4: hypergraph closed-form epilogue -> e4m3 feat ------------------
__global__ void epilogue(const float* __restrict__ Z, const float* __restrict__ hg_b,
                         const float* __restrict__ sim, const float* __restrict__ rlabel,
                         const float* __restrict__ lbl_w, const float* __restrict__ lbl_b,
                         uint8_t* __restrict__ F)
{
    int b = blockIdx.x;
    __shared__ float sw[RNUM];
    __shared__ float slbl;
    if (threadIdx.x == 0) {
        float mx = -1e30f;
        for (int i = 0; i < RNUM; i++) mx = fmaxf(mx, sim[b * RNUM + i]);
        float s = 0.f;
        for (int i = 0; i < RNUM; i++) { sw[i] = expf(sim[b * RNUM + i] - mx); s += sw[i]; }
        float inv = 1.f / s;
        float la = 0.f;
        for (int i = 0; i < RNUM; i++) { sw[i] *= inv; la += sw[i] * rlabel[b * RNUM + i]; }
        slbl = la;
    }
    __syncthreads();
    float lblagg = slbl;

    for (int d = threadIdx.x; d < ZD; d += blockDim.x) {
        float hb = hg_b[d];
        size_t ro = (size_t)b * 6 * ZD;
        float xt_t = Z[ro + 0 * ZD + d] + hb;
        float xt_v = Z[ro + 1 * ZD + d] + hb;
        float xt_u = Z[ro + 2 * ZD + d] + hb;
        float s1   = Z[ro + 3 * ZD + d] + 10.f * hb;
        float s2   = Z[ro + 4 * ZD + d] + 10.f * hb;
        float s3   = Z[ro + 5 * ZD + d] + 10.f * hb;

        float yg0 = (xt_t + xt_v + xt_u) * (1.f / 3.f);
        float yg1 = (s1 + xt_t) * (1.f / 11.f);
        float yg2 = (s2 + xt_v) * (1.f / 11.f);
        float yg3 = (s3 + xt_u) * (1.f / 11.f);

        float xo0 = fmaxf(0.5f * (yg0 + yg1), 0.f);
        float xo1 = fmaxf(0.5f * (yg0 + yg2), 0.f);
        float xo2 = fmaxf(0.5f * (yg0 + yg3), 0.f);

        float rt_agg, rv_agg;
        if (b == 0) {
            rt_agg = 0.f; rv_agg = 0.f;
#pragma unroll
            for (int i = 0; i < RNUM; i++) {
                float xt_rt = Z[(size_t)(M_BASE + i) * ZD + d] + hb;
                float xt_rv = Z[(size_t)(M_BASE + RNUM + i) * ZD + d] + hb;
                float yp = 0.5f * (xt_rt + xt_rv);
                rt_agg += sw[i] * fmaxf(0.5f * (yg1 + yp), 0.f);
                rv_agg += sw[i] * fmaxf(0.5f * (yg2 + yp), 0.f);
            }
        } else {
            rt_agg = fmaxf(yg1, 0.f);
            rv_agg = fmaxf(yg2, 0.f);
        }
        float ru_agg = fmaxf(yg3, 0.f);
        float le = fmaxf(lbl_w[d] * lblagg + lbl_b[d], 0.f);

        uint8_t* Fr = F + (size_t)b * P1K;
        Fr[          d] = (uint8_t)(f8pack2(xo0, 0.f) & 0xFF);
        Fr[ 300 +    d] = (uint8_t)(f8pack2(xo1, 0.f) & 0xFF);
        Fr[ 600 +    d] = (uint8_t)(f8pack2(xo2, 0.f) & 0xFF);
        Fr[ 900 +    d] = (uint8_t)(f8pack2(rv_agg, 0.f) & 0xFF);
        Fr[1200 +    d] = (uint8_t)(f8pack2(rt_agg, 0.f) & 0xFF);
        Fr[1500 +    d] = (uint8_t)(f8pack2(ru_agg, 0.f) & 0xFF);
        Fr[1800 +    d] = (uint8_t)(f8pack2(le, 0.f) & 0xFF);
    }
}

// ------------ final 200->1 dot + sigmoid ---------------------------------------
__global__ void final_head(const float* __restrict__ H2, const float* __restrict__ w,
                           const float* __restrict__ b, float* __restrict__ out)
{
    int row  = blockIdx.x * (blockDim.x >> 5) + (threadIdx.x >> 5);
    int lane = threadIdx.x & 31;
    if (row >= BSZ) return;
    float s = 0.f;
    for (int j = lane; j < 200; j += 32) s += H2[(size_t)row * 200 + j] * w[j];
#pragma unroll
    for (int off = 16; off > 0; off >>= 1)
        s += __shfl_xor_sync(0xFFFFFFFFu, s, off);
    if (lane == 0) out[row] = 1.f / (1.f + expf(-(s + b[0])));
}

// -------------------------------- launch ---------------------------------------
extern "C" void kernel_launch(void* const* d_in, const int* in_sizes, int n_in,
                              void* d_out, int out_size)
{
    const float* visual  = (const float*)d_in[0];
    const float* textual = (const float*)d_in[1];
    const float* sim     = (const float*)d_in[2];
    const float* rvis    = (const float*)d_in[3];
    const float* rtxt    = (const float*)d_in[4];
    const float* rlabel  = (const float*)d_in[5];
    const float* user    = (const float*)d_in[6];
    const float* ruser   = (const float*)d_in[7];
    const float* vis_w = (const float*)d_in[9],  *vis_b = (const float*)d_in[10];
    const float* txt_w = (const float*)d_in[11], *txt_b = (const float*)d_in[12];
    const float* usr_w = (const float*)d_in[13], *usr_b = (const float*)d_in[14];
    const float* rvis_w = (const float*)d_in[15], *rvis_b = (const float*)d_in[16];
    const float* rtxt_w = (const float*)d_in[17], *rtxt_b = (const float*)d_in[18];
    const float* rusr_w = (const float*)d_in[19], *rusr_b = (const float*)d_in[20];
    const float* hg_w = (const float*)d_in[21], *hg_b = (const float*)d_in[22];
    const float* lbl_w = (const float*)d_in[23], *lbl_b = (const float*)d_in[24];
    const float* p1_w = (const float*)d_in[25], *p1_b = (const float*)d_in[26];
    const float* p2_w = (const float*)d_in[27], *p2_b = (const float*)d_in[28];
    const float* p3_w = (const float*)d_in[29], *p3_b = (const float*)d_in[30];

    float *mbuf, *z, *h2;
    uint8_t *abf, *bbf, *hgA, *hgW, *p1A, *p1W, *p2A, *p2W;
    cudaGetSymbolAddress((void**)&abf,  g_Abf);
    cudaGetSymbolAddress((void**)&bbf,  g_Bbf);
    cudaGetSymbolAddress((void**)&mbuf, g_M);
    cudaGetSymbolAddress((void**)&hgA,  g_hgA);
    cudaGetSymbolAddress((void**)&hgW,  g_hgW);
    cudaGetSymbolAddress((void**)&z,    g_Z);
    cudaGetSymbolAddress((void**)&p1A,  g_p1A);
    cudaGetSymbolAddress((void**)&p1W,  g_p1W);
    cudaGetSymbolAddress((void**)&p2A,  g_p2A);
    cudaGetSymbolAddress((void**)&p2W,  g_p2W);
    cudaGetSymbolAddress((void**)&h2,   g_H2);

    cudaFuncSetAttribute(proj_gemm, cudaFuncAttributeMaxDynamicSharedMemorySize, SMEM_REQ);
    cudaFuncSetAttribute(mma_gemm1, cudaFuncAttributeMaxDynamicSharedMemorySize, SMEM_REQ);

    const int CT = 256;
    // zero targets: M (atomics), p1A/p2A pad columns
    cudaMemsetAsync(mbuf, 0, (size_t)M_ROWS * PD * sizeof(float));
    cudaMemsetAsync(p1A, 0, (size_t)BSZ * P1K);
    cudaMemsetAsync(p2A, 0, (size_t)BSZ * P2K);

    // ---- convert inputs to e4m3 ----
    auto cv = [&](const float* src, uint8_t* dst, int rows_src, int Kreal, int Kpad) {
        long long tot4 = (long long)((Kpad >> 2)) *
                         ((Kpad == Kreal) ? rows_src : rows_src) ;
        (void)tot4;
    };
    auto cvrun = [&](const float* src, uint8_t* dst, long long rows_dst,
                     int rows_src, int Kreal, int Kpad) {
        long long tot4 = rows_dst * (Kpad >> 2);
        conv_f8<<<(unsigned)((tot4 + CT - 1) / CT), CT>>>(src, dst, rows_src, Kreal, Kpad, tot4);
    };
    cvrun(textual, abf + (size_t)T_OFF  * FD, BSZ,        BSZ,        FD, FD);
    cvrun(visual,  abf + (size_t)V_OFF  * FD, BSZ,        BSZ,        FD, FD);
    cvrun(user,    abf + (size_t)U_OFF  * FD, BSZ,        BSZ,        FD, FD);
    cvrun(rtxt,    abf + (size_t)RT_OFF * FD, BSZ * RNUM, BSZ * RNUM, FD, FD);
    cvrun(rvis,    abf + (size_t)RV_OFF * FD, BSZ * RNUM, BSZ * RNUM, FD, FD);
    cvrun(ruser,   abf + (size_t)RU_OFF * FD, BSZ * UNUM, BSZ * UNUM, FD, FD);

    // ---- convert weights to e4m3 (zero padded) ----
    const float* ws[6] = {txt_w, vis_w, usr_w, rtxt_w, rvis_w, rusr_w};
    for (int i = 0; i < 6; i++)
        cvrun(ws[i], bbf + (size_t)i * 512 * FD, 512, PD, FD, FD);
    cvrun(hg_w, hgW, 384, ZD, PD, 512);
    cvrun(p1_w, p1W, 896, 800, 2100, P1K);
    cvrun(p2_w, p2W, 256, 200, 800, P2K);

    // ---- unified projection GEMM (6 segments, fused tanh + group-sum) ----
    {
        ProjArgs pa;
        pa.A = abf;
        for (int i = 0; i < 6; i++) pa.B[i] = bbf + (size_t)i * 512 * FD;
        pa.bias[0] = txt_b; pa.bias[1] = vis_b; pa.bias[2] = usr_b;
        pa.bias[3] = rtxt_b; pa.bias[4] = rvis_b; pa.bias[5] = rusr_b;
        pa.Mo = mbuf;
        dim3 g(4, 1056);
        proj_gemm<<<g, 256, SMEM_REQ>>>(pa);
    }

    // ---- hg: conv A then GEMM (bias handled in epilogue) ----
    cvrun(mbuf, hgA, M_PAD_HG, M_ROWS, PD, 512);
    {
        dim3 g(3, M_PAD_HG / 128);
        mma_gemm1<<<g, 256, SMEM_REQ>>>(hgA, hgW, nullptr, z, M_ROWS, ZD, ZD, 512, 0, 0);
    }

    // ---- closed-form hypergraph conv + feat assembly (e4m3 out) ----
    epilogue<<<BSZ, 128>>>(z, hg_b, sim, rlabel, lbl_w, lbl_b, p1A);

    // ---- p1: relu, e4m3 out into p2A (stride P2K) ----
    {
        dim3 g(7, BSZ / 128);
        mma_gemm1<<<g, 256, SMEM_REQ>>>(p1A, p1W, p1_b, p2A, BSZ, 800, P2K, P1K, 2, 1);
    }
    // ---- p2: relu, fp32 out ----
    {
        dim3 g(2, BSZ / 128);
        mma_gemm1<<<g, 256, SMEM_REQ>>>(p2A, p2W, p2_b, h2, BSZ, 200, 200, P2K, 2, 0);
    }
    // ---- sigmoid head ----
    final_head<<<(BSZ * 32 + 255) / 256, 256>>>(h2, p3_w, p3_b, (float*)d_out);
}

// round 16
// speedup vs baseline: 1.2683x; 1.2683x over previous
#include <cuda_runtime.h>
#include <cuda_bf16.h>
#include <cstdint>
#include <math.h>

#define BSZ   4096
#define FD    768
#define PD    500
#define ZD    300
#define RNUM  10
#define UNUM  10

// A segment row offsets (order: t, v, u, rt, rv, ru)
#define T_OFF   0
#define V_OFF   4096
#define U_OFF   8192
#define RT_OFF  12288
#define RV_OFF  53248
#define RU_OFF  94208
#define XP_ROWS 135168
#define M_BASE  24576          // 4096*6 compact rows
#define M_ROWS  24596          // + 20 sample-0 pair rows
#define M_PAD_HG 24704         // 193*128

// -------------------- static scratch (no allocations allowed) -------------------
__device__ __nv_bfloat16 g_Abf[(size_t)XP_ROWS * FD];      // proj inputs bf16
__device__ __nv_bfloat16 g_Bbf[6 * 512 * FD];              // proj weights bf16
__device__ float g_M [(size_t)M_ROWS  * PD];               // group-summed tanh outputs
__device__ __nv_bfloat16 g_hgA[(size_t)M_PAD_HG * 512];    // hg A bf16 (Kpad 512)
__device__ __nv_bfloat16 g_hgW[(size_t)384 * 512];
__device__ float g_Z  [(size_t)M_ROWS  * ZD];
__device__ __nv_bfloat16 g_p1A[(size_t)BSZ * 2112];        // feat bf16 (Kpad 2112)
__device__ __nv_bfloat16 g_p1W[(size_t)896 * 2112];
__device__ __nv_bfloat16 g_p2A[(size_t)BSZ * 832];         // h1 bf16 (Kpad 832)
__device__ __nv_bfloat16 g_p2W[(size_t)256 * 832];
__device__ float g_H2 [(size_t)BSZ * 200];

__constant__ int c_rowbase[6] = {T_OFF, V_OFF, U_OFF, RT_OFF, RV_OFF, RU_OFF};

// ============================ PTX helpers =======================================
__device__ __forceinline__ uint32_t smem_u32(const void* p) {
    uint32_t a;
    asm("{ .reg .u64 t; cvta.to.shared.u64 t, %1; cvt.u32.u64 %0, t; }" : "=r"(a) : "l"(p));
    return a;
}
__device__ __forceinline__ void cp16(uint32_t dst, const void* src) {
    asm volatile("cp.async.cg.shared.global [%0], [%1], 16;" :: "r"(dst), "l"(src));
}
#define CP_COMMIT() asm volatile("cp.async.commit_group;" ::: "memory")
#define CP_WAIT0()  asm volatile("cp.async.wait_group 0;" ::: "memory")
#define CP_WAIT1()  asm volatile("cp.async.wait_group 1;" ::: "memory")

__device__ __forceinline__ void ldsm_x4(uint32_t& r0, uint32_t& r1, uint32_t& r2, uint32_t& r3,
                                        uint32_t addr) {
    asm volatile("ldmatrix.sync.aligned.m8n8.x4.shared.b16 {%0,%1,%2,%3}, [%4];"
                 : "=r"(r0), "=r"(r1), "=r"(r2), "=r"(r3) : "r"(addr));
}
__device__ __forceinline__ void mma16816(float* d, const uint32_t* a, const uint32_t* b) {
    asm volatile("mma.sync.aligned.m16n8k16.row.col.f32.bf16.bf16.f32 "
                 "{%0,%1,%2,%3}, {%4,%5,%6,%7}, {%8,%9}, {%0,%1,%2,%3};"
                 : "+f"(d[0]), "+f"(d[1]), "+f"(d[2]), "+f"(d[3])
                 : "r"(a[0]), "r"(a[1]), "r"(a[2]), "r"(a[3]), "r"(b[0]), "r"(b[1]));
}
#define SWZ128(b)  ((b) ^ (((b) >> 3) & 0x70))
#define SM_STAGE 32768   // A(16K) + B(16K)
#define SMEM_REQ 69632   // 2 stages + room for 128x132 fp32 reduction staging

// chunk load: 128x64 A tile + 128x64 B tile (bf16, SW128)
__device__ __forceinline__ void load_chunk1(
    const __nv_bfloat16* __restrict__ A, const __nv_bfloat16* __restrict__ B,
    int strideA, int strideB, int koff, int n0, uint32_t sbase, int tid)
{
    const int r = tid >> 3, q = tid & 7;
    const uint32_t sa = sbase + SWZ128(r * 128 + q * 16);
    const uint32_t sbB = sbase + 16384 + SWZ128(r * 128 + q * 16);
#pragma unroll
    for (int i = 0; i < 4; i++)
        cp16(sa + i * 4096, A + (size_t)(r + i * 32) * strideA + koff + q * 8);
#pragma unroll
    for (int i = 0; i < 4; i++)
        cp16(sbB + i * 4096, B + (size_t)(n0 + r + i * 32) * strideB + koff + q * 8);
}

// compute one 64-K chunk (pure bf16)
__device__ __forceinline__ void compute_chunk1(uint32_t base, int warp_m, int warp_n,
                                               int lane, float acc[4][4][4])
{
#pragma unroll
    for (int ks = 0; ks < 4; ks++) {
        uint32_t a[4][4], b[2][4];
#pragma unroll
        for (int mt = 0; mt < 4; mt++) {
            int row = warp_m * 64 + mt * 16 + (lane & 15);
            int byo = row * 128 + ks * 32 + ((lane >> 4) & 1) * 16;
            ldsm_x4(a[mt][0], a[mt][1], a[mt][2], a[mt][3], base + SWZ128(byo));
        }
#pragma unroll
        for (int np = 0; np < 2; np++) {
            int nrow = warp_n * 32 + np * 16 + ((lane >> 4) & 1) * 8 + (lane & 7);
            int byo = nrow * 128 + ks * 32 + ((lane >> 3) & 1) * 16;
            ldsm_x4(b[np][0], b[np][1], b[np][2], b[np][3], base + 16384 + SWZ128(byo));
        }
#pragma unroll
        for (int mt = 0; mt < 4; mt++)
#pragma unroll
            for (int nt = 0; nt < 4; nt++)
                mma16816(acc[mt][nt], a[mt], &b[nt >> 1][(nt & 1) * 2]);
    }
}

// ======================= conversion kernels =====================================
__global__ void conv_hi(const float* __restrict__ src, __nv_bfloat16* __restrict__ dst,
                        int nrows)   // [nrows x 768] fp32 -> bf16
{
    int i = blockIdx.x * blockDim.x + threadIdx.x;
    int total = nrows * (FD / 4);
    if (i >= total) return;
    int row = i / (FD / 4), c4 = (i % (FD / 4)) * 4;
    float4 x = *reinterpret_cast<const float4*>(src + (size_t)row * FD + c4);
    __nv_bfloat162 p0, p1;
    p0.x = __float2bfloat16(x.x); p0.y = __float2bfloat16(x.y);
    p1.x = __float2bfloat16(x.z); p1.y = __float2bfloat16(x.w);
    uint2 v;
    v.x = *reinterpret_cast<uint32_t*>(&p0);
    v.y = *reinterpret_cast<uint32_t*>(&p1);
    *reinterpret_cast<uint2*>(dst + (size_t)row * FD + c4) = v;
}

// float [rows_src x Kreal] -> bf16 [rows_dst x Kpad], zero padded
__global__ void conv_hi_pad(const float* __restrict__ src, __nv_bfloat16* __restrict__ dst,
                            int rows_src, int Kreal, int Kpad, long long total)
{
    long long i = (long long)blockIdx.x * blockDim.x + threadIdx.x;
    if (i >= total) return;
    int col = (int)(i % Kpad);
    long long row = i / Kpad;
    float x = (row < rows_src && col < Kreal) ? src[row * Kreal + col] : 0.f;
    dst[row * Kpad + col] = __float2bfloat16(x);
}

// ================= unified projection GEMM (6 segments, fused epilogue) =========
struct ProjArgs {
    const __nv_bfloat16* A;
    const __nv_bfloat16* B[6];
    const float* bias[6];
    float* Mo;
};

__global__ __launch_bounds__(256, 2) void proj_gemm(ProjArgs args)
{
    extern __shared__ char smem[];
    const uint32_t sb = smem_u32(smem);
    const int tid = threadIdx.x, lane = tid & 31, wid = tid >> 5;
    const int warp_m = wid >> 2, warp_n = wid & 3;
    const int n0 = blockIdx.x * 128;
    const int ty = blockIdx.y;

    int seg, tstart;
    if (ty < 96)       { seg = ty >> 5; tstart = seg << 5; }
    else if (ty < 416) { seg = 3; tstart = 96; }
    else if (ty < 736) { seg = 4; tstart = 416; }
    else               { seg = 5; tstart = 736; }
    const int tl = ty - tstart;
    const __nv_bfloat16* A = args.A + (size_t)(c_rowbase[seg] + tl * 128) * FD;
    const __nv_bfloat16* B = args.B[seg];
    const float* bias = args.bias[seg];
    float* Mo = args.Mo;

    float acc[4][4][4];
#pragma unroll
    for (int i = 0; i < 4; i++)
#pragma unroll
        for (int j = 0; j < 4; j++)
#pragma unroll
            for (int k = 0; k < 4; k++) acc[i][j][k] = 0.f;

    const int kc = 12;   // 768/64
    load_chunk1(A, B, FD, FD, 0, n0, sb, tid);
    CP_COMMIT();
    for (int c = 0; c < kc; c++) {
        if (c + 1 < kc) {
            load_chunk1(A, B, FD, FD, (c + 1) * 64, n0, sb + ((c + 1) & 1) * SM_STAGE, tid);
            CP_COMMIT();
            CP_WAIT1();
        } else CP_WAIT0();
        __syncthreads();
        compute_chunk1(sb + (c & 1) * SM_STAGE, warp_m, warp_n, lane, acc);
        __syncthreads();
    }

    if (seg < 3) {
        // direct: one row per sample -> g_M[(b*6+seg)*500 + n]
#pragma unroll
        for (int mt = 0; mt < 4; mt++) {
            int r0 = warp_m * 64 + mt * 16 + (lane >> 2);
#pragma unroll
            for (int nt = 0; nt < 4; nt++) {
                int c0 = warp_n * 32 + nt * 8 + (lane & 3) * 2;
#pragma unroll
                for (int q = 0; q < 4; q++) {
                    int r = r0 + ((q >> 1) ? 8 : 0);
                    int cc = n0 + c0 + (q & 1);
                    if (cc < PD) {
                        float v = tanhf(acc[mt][nt][q] + bias[cc]);
                        Mo[((size_t)(tl * 128 + r) * 6 + seg) * PD + cc] = v;
                    }
                }
            }
        }
    } else {
        // reduce: stage tanh values in smem, sum per sample, atomicAdd
        float* sred = (float*)smem;
#pragma unroll
        for (int mt = 0; mt < 4; mt++) {
            int r0 = warp_m * 64 + mt * 16 + (lane >> 2);
#pragma unroll
            for (int nt = 0; nt < 4; nt++) {
                int c0 = warp_n * 32 + nt * 8 + (lane & 3) * 2;
#pragma unroll
                for (int q = 0; q < 4; q++) {
                    int r = r0 + ((q >> 1) ? 8 : 0);
                    int cl = c0 + (q & 1);
                    int cc = n0 + cl;
                    float v = tanhf(acc[mt][nt][q] + bias[cc < PD ? cc : PD - 1]);
                    sred[r * 132 + cl] = v;
                }
            }
        }
        __syncthreads();
        const int r0g = tl * 128;
        const int sfirst = r0g / 10, slast = (r0g + 127) / 10;
        const int ns = slast - sfirst + 1;
        for (int idx = tid; idx < ns * 128; idx += 256) {
            int si = idx >> 7, cl = idx & 127;
            int cc = n0 + cl;
            if (cc >= PD) continue;
            int s = sfirst + si;
            int lo = s * 10 - r0g;     if (lo < 0) lo = 0;
            int hi = s * 10 + 9 - r0g; if (hi > 127) hi = 127;
            float sum = 0.f;
            for (int r = lo; r <= hi; r++) sum += sred[r * 132 + cl];
            atomicAdd(&Mo[((size_t)s * 6 + seg) * PD + cc], sum);
        }
        if (tl == 0 && seg != 5) {
            int rb = (seg == 3) ? M_BASE : M_BASE + RNUM;
            for (int idx = tid; idx < 10 * 128; idx += 256) {
                int r = idx >> 7, cl = idx & 127;
                int cc = n0 + cl;
                if (cc < PD) Mo[((size_t)(rb + r)) * PD + cc] = sred[r * 132 + cl];
            }
        }
    }
}

// ===================== generic bf16 HMMA GEMM ===================================
__global__ __launch_bounds__(256, 2) void mma_gemm1(
    const __nv_bfloat16* __restrict__ A, const __nv_bfloat16* __restrict__ B,
    const float* __restrict__ bias, void* __restrict__ Cout,
    int M, int Nreal, int ostride, int Kpad, int act, int outbf16)
{
    extern __shared__ char smem[];
    const uint32_t sb = smem_u32(smem);
    const int tid = threadIdx.x, lane = tid & 31, wid = tid >> 5;
    const int warp_m = wid >> 2, warp_n = wid & 3;
    const int m0 = blockIdx.y * 128, n0 = blockIdx.x * 128;
    const __nv_bfloat16* At = A + (size_t)m0 * Kpad;
    const int kc = Kpad >> 6;

    float acc[4][4][4];
#pragma unroll
    for (int i = 0; i < 4; i++)
#pragma unroll
        for (int j = 0; j < 4; j++)
#pragma unroll
            for (int k = 0; k < 4; k++) acc[i][j][k] = 0.f;

    load_chunk1(At, B, Kpad, Kpad, 0, n0, sb, tid);
    CP_COMMIT();
    for (int c = 0; c < kc; c++) {
        if (c + 1 < kc) {
            load_chunk1(At, B, Kpad, Kpad, (c + 1) * 64, n0,
                        sb + ((c + 1) & 1) * SM_STAGE, tid);
            CP_COMMIT();
            CP_WAIT1();
        } else CP_WAIT0();
        __syncthreads();
        compute_chunk1(sb + (c & 1) * SM_STAGE, warp_m, warp_n, lane, acc);
        __syncthreads();
    }

#pragma unroll
    for (int mt = 0; mt < 4; mt++) {
        int r0 = m0 + warp_m * 64 + mt * 16 + (lane >> 2);
#pragma unroll
        for (int nt = 0; nt < 4; nt++) {
            int c0 = n0 + warp_n * 32 + nt * 8 + (lane & 3) * 2;
#pragma unroll
            for (int q = 0; q < 4; q++) {
                int r = r0 + ((q >> 1) ? 8 : 0);
                int cc = c0 + (q & 1);
                if (r < M && cc < Nreal) {
                    float v = acc[mt][nt][q];
                    if (bias) v += bias[cc];
                    if (act == 1)      v = tanhf(v);
                    else if (act == 2) v = fmaxf(v, 0.f);
                    if (outbf16)
                        ((__nv_bfloat16*)Cout)[(size_t)r * ostride + cc] = __float2bfloat16(v);
                    else
                        ((float*)Cout)[(size_t)r * ostride + cc] = v;
                }
            }
        }
    }
}

// ------------ K4: hypergraph closed-form epilogue -> bf16 feat ------------------
__global__ void epilogue(const float* __restrict__ Z, const float* __restrict__ hg_b,
                         const float* __restrict__ sim, const float* __restrict__ rlabel,
                         const float* __restrict__ lbl_w, const float* __restrict__ lbl_b,
                         __nv_bfloat16* __restrict__ F)
{
    int b = blockIdx.x;
    __shared__ float sw[RNUM];
    __shared__ float slbl;
    if (threadIdx.x == 0) {
        float mx = -1e30f;
        for (int i = 0; i < RNUM; i++) mx = fmaxf(mx, sim[b * RNUM + i]);
        float s = 0.f;
        for (int i = 0; i < RNUM; i++) { sw[i] = expf(sim[b * RNUM + i] - mx); s += sw[i]; }
        float inv = 1.f / s;
        float la = 0.f;
        for (int i = 0; i < RNUM; i++) { sw[i] *= inv; la += sw[i] * rlabel[b * RNUM + i]; }
        slbl = la;
    }
    __syncthreads();
    float lblagg = slbl;

    for (int d = threadIdx.x; d < ZD; d += blockDim.x) {
        float hb = hg_b[d];
        size_t ro = (size_t)b * 6 * ZD;
        float xt_t = Z[ro + 0 * ZD + d] + hb;
        float xt_v = Z[ro + 1 * ZD + d] + hb;
        float xt_u = Z[ro + 2 * ZD + d] + hb;
        float s1   = Z[ro + 3 * ZD + d] + 10.f * hb;
        float s2   = Z[ro + 4 * ZD + d] + 10.f * hb;
        float s3   = Z[ro + 5 * ZD + d] + 10.f * hb;

        float yg0 = (xt_t + xt_v + xt_u) * (1.f / 3.f);
        float yg1 = (s1 + xt_t) * (1.f / 11.f);
        float yg2 = (s2 + xt_v) * (1.f / 11.f);
        float yg3 = (s3 + xt_u) * (1.f / 11.f);

        float xo0 = fmaxf(0.5f * (yg0 + yg1), 0.f);
        float xo1 = fmaxf(0.5f * (yg0 + yg2), 0.f);
        float xo2 = fmaxf(0.5f * (yg0 + yg3), 0.f);

        float rt_agg, rv_agg;
        if (b == 0) {
            rt_agg = 0.f; rv_agg = 0.f;
#pragma unroll
            for (int i = 0; i < RNUM; i++) {
                float xt_rt = Z[(size_t)(M_BASE + i) * ZD + d] + hb;
                float xt_rv = Z[(size_t)(M_BASE + RNUM + i) * ZD + d] + hb;
                float yp = 0.5f * (xt_rt + xt_rv);
                rt_agg += sw[i] * fmaxf(0.5f * (yg1 + yp), 0.f);
                rv_agg += sw[i] * fmaxf(0.5f * (yg2 + yp), 0.f);
            }
        } else {
            rt_agg = fmaxf(yg1, 0.f);
            rv_agg = fmaxf(yg2, 0.f);
        }
        float ru_agg = fmaxf(yg3, 0.f);
        float le = fmaxf(lbl_w[d] * lblagg + lbl_b[d], 0.f);

        __nv_bfloat16* Fr = F + (size_t)b * 2112;
        Fr[          d] = __float2bfloat16(xo0);
        Fr[ 300 +    d] = __float2bfloat16(xo1);
        Fr[ 600 +    d] = __float2bfloat16(xo2);
        Fr[ 900 +    d] = __float2bfloat16(rv_agg);
        Fr[1200 +    d] = __float2bfloat16(rt_agg);
        Fr[1500 +    d] = __float2bfloat16(ru_agg);
        Fr[1800 +    d] = __float2bfloat16(le);
    }
}

// ------------ final 200->1 dot + sigmoid ---------------------------------------
__global__ void final_head(const float* __restrict__ H2, const float* __restrict__ w,
                           const float* __restrict__ b, float* __restrict__ out)
{
    int row  = blockIdx.x * (blockDim.x >> 5) + (threadIdx.x >> 5);
    int lane = threadIdx.x & 31;
    if (row >= BSZ) return;
    float s = 0.f;
    for (int j = lane; j < 200; j += 32) s += H2[(size_t)row * 200 + j] * w[j];
#pragma unroll
    for (int off = 16; off > 0; off >>= 1)
        s += __shfl_xor_sync(0xFFFFFFFFu, s, off);
    if (lane == 0) out[row] = 1.f / (1.f + expf(-(s + b[0])));
}

// -------------------------------- launch ---------------------------------------
extern "C" void kernel_launch(void* const* d_in, const int* in_sizes, int n_in,
                              void* d_out, int out_size)
{
    const float* visual  = (const float*)d_in[0];
    const float* textual = (const float*)d_in[1];
    const float* sim     = (const float*)d_in[2];
    const float* rvis    = (const float*)d_in[3];
    const float* rtxt    = (const float*)d_in[4];
    const float* rlabel  = (const float*)d_in[5];
    const float* user    = (const float*)d_in[6];
    const float* ruser   = (const float*)d_in[7];
    const float* vis_w = (const float*)d_in[9],  *vis_b = (const float*)d_in[10];
    const float* txt_w = (const float*)d_in[11], *txt_b = (const float*)d_in[12];
    const float* usr_w = (const float*)d_in[13], *usr_b = (const float*)d_in[14];
    const float* rvis_w = (const float*)d_in[15], *rvis_b = (const float*)d_in[16];
    const float* rtxt_w = (const float*)d_in[17], *rtxt_b = (const float*)d_in[18];
    const float* rusr_w = (const float*)d_in[19], *rusr_b = (const float*)d_in[20];
    const float* hg_w = (const float*)d_in[21], *hg_b = (const float*)d_in[22];
    const float* lbl_w = (const float*)d_in[23], *lbl_b = (const float*)d_in[24];
    const float* p1_w = (const float*)d_in[25], *p1_b = (const float*)d_in[26];
    const float* p2_w = (const float*)d_in[27], *p2_b = (const float*)d_in[28];
    const float* p3_w = (const float*)d_in[29], *p3_b = (const float*)d_in[30];

    float *mbuf, *z, *h2;
    __nv_bfloat16 *abf, *bbf, *hgA, *hgW, *p1A, *p1W, *p2A, *p2W;
    cudaGetSymbolAddress((void**)&abf,  g_Abf);
    cudaGetSymbolAddress((void**)&bbf,  g_Bbf);
    cudaGetSymbolAddress((void**)&mbuf, g_M);
    cudaGetSymbolAddress((void**)&hgA,  g_hgA);
    cudaGetSymbolAddress((void**)&hgW,  g_hgW);
    cudaGetSymbolAddress((void**)&z,    g_Z);
    cudaGetSymbolAddress((void**)&p1A,  g_p1A);
    cudaGetSymbolAddress((void**)&p1W,  g_p1W);
    cudaGetSymbolAddress((void**)&p2A,  g_p2A);
    cudaGetSymbolAddress((void**)&p2W,  g_p2W);
    cudaGetSymbolAddress((void**)&h2,   g_H2);

    cudaFuncSetAttribute(proj_gemm, cudaFuncAttributeMaxDynamicSharedMemorySize, SMEM_REQ);
    cudaFuncSetAttribute(mma_gemm1, cudaFuncAttributeMaxDynamicSharedMemorySize, SMEM_REQ);

    const int CT = 256;
    // zero accumulation target (atomics add into it)
    cudaMemsetAsync(mbuf, 0, (size_t)M_ROWS * PD * sizeof(float));

    // ---- convert inputs to bf16 ----
    auto cvA = [&](const float* src, int doff, int rows) {
        int tot = rows * (FD / 4);
        conv_hi<<<(tot + CT - 1) / CT, CT>>>(src, abf + (size_t)doff * FD, rows);
    };
    cvA(textual, T_OFF,  BSZ);
    cvA(visual,  V_OFF,  BSZ);
    cvA(user,    U_OFF,  BSZ);
    cvA(rtxt,    RT_OFF, BSZ * RNUM);
    cvA(rvis,    RV_OFF, BSZ * RNUM);
    cvA(ruser,   RU_OFF, BSZ * UNUM);

    // ---- convert weights to bf16 (padded) ----
    const float* ws[6] = {txt_w, vis_w, usr_w, rtxt_w, rvis_w, rusr_w};
    for (int i = 0; i < 6; i++) {
        long long tot = (long long)512 * FD;
        conv_hi_pad<<<(unsigned)((tot + CT - 1) / CT), CT>>>(
            ws[i], bbf + (size_t)i * 512 * FD, PD, FD, FD, tot);
    }
    {
        long long tot = (long long)384 * 512;
        conv_hi_pad<<<(unsigned)((tot + CT - 1) / CT), CT>>>(hg_w, hgW, ZD, PD, 512, tot);
        tot = (long long)896 * 2112;
        conv_hi_pad<<<(unsigned)((tot + CT - 1) / CT), CT>>>(p1_w, p1W, 800, 2100, 2112, tot);
        tot = (long long)256 * 832;
        conv_hi_pad<<<(unsigned)((tot + CT - 1) / CT), CT>>>(p2_w, p2W, 200, 800, 832, tot);
    }

    // ---- unified projection GEMM (6 segments, fused tanh + group-sum) ----
    {
        ProjArgs pa;
        pa.A = abf;
        for (int i = 0; i < 6; i++) pa.B[i] = bbf + (size_t)i * 512 * FD;
        pa.bias[0] = txt_b; pa.bias[1] = vis_b; pa.bias[2] = usr_b;
        pa.bias[3] = rtxt_b; pa.bias[4] = rvis_b; pa.bias[5] = rusr_b;
        pa.Mo = mbuf;
        dim3 g(4, 1056);
        proj_gemm<<<g, 256, SMEM_REQ>>>(pa);
    }

    // ---- hg: conv A then GEMM (bias handled in epilogue) ----
    {
        long long tot = (long long)M_PAD_HG * 512;
        conv_hi_pad<<<(unsigned)((tot + CT - 1) / CT), CT>>>(mbuf, hgA, M_ROWS, PD, 512, tot);
        dim3 g(3, M_PAD_HG / 128);
        mma_gemm1<<<g, 256, SMEM_REQ>>>(hgA, hgW, nullptr, z, M_ROWS, ZD, ZD, 512, 0, 0);
    }

    // ---- closed-form hypergraph conv + feat assembly (bf16 out) ----
    epilogue<<<BSZ, 128>>>(z, hg_b, sim, rlabel, lbl_w, lbl_b, p1A);

    // ---- p1: relu, bf16 out into p2A (stride 832) ----
    {
        dim3 g(7, BSZ / 128);
        mma_gemm1<<<g, 256, SMEM_REQ>>>(p1A, p1W, p1_b, p2A, BSZ, 800, 832, 2112, 2, 1);
    }
    // ---- p2: relu, fp32 out ----
    {
        dim3 g(2, BSZ / 128);
        mma_gemm1<<<g, 256, SMEM_REQ>>>(p2A, p2W, p2_b, h2, BSZ, 200, 200, 832, 2, 0);
    }
    // ---- sigmoid head ----
    final_head<<<(BSZ * 32 + 255) / 256, 256>>>(h2, p3_w, p3_b, (float*)d_out);
}